// round 10
// baseline (speedup 1.0000x reference)
#include <cuda_runtime.h>
#include <cuda_fp16.h>
#include <cstdint>

#define N_NODES 8192
#define DF 128

// ---------------- scratch (static __device__ globals: allocation-free) -------
__device__ float  g_s[N_NODES];                           // 32 KB : d_inv_sqrt
__device__ __half g_adj_h[(size_t)N_NODES * N_NODES];     // 128 MB: fp16 adjacency
__device__ __half g_yth[(size_t)DF * N_NODES];            // 2 MB  : (s_j*(xW^T))^T [d][j]

// ---------------- helpers ----------------------------------------------------
__device__ __forceinline__ uint32_t smem_u32(const void* p) {
    uint32_t a;
    asm("{ .reg .u64 t; cvta.to.shared.u64 t, %1; cvt.u32.u64 %0, t; }"
        : "=r"(a) : "l"(p));
    return a;
}

__device__ __forceinline__ void cp_async16(uint32_t saddr, const void* gaddr) {
    asm volatile("cp.async.cg.shared.global [%0], [%1], 16;" :: "r"(saddr), "l"(gaddr));
}
__device__ __forceinline__ void cp_commit() {
    asm volatile("cp.async.commit_group;" ::: "memory");
}

__device__ __forceinline__ uint32_t f2h2(float lo, float hi) {
    uint32_t r;
    asm("cvt.rn.f16x2.f32 %0, %1, %2;" : "=r"(r) : "f"(hi), "f"(lo));
    return r;
}

#define LDSM_X4(r0, r1, r2, r3, addr) \
    asm volatile("ldmatrix.sync.aligned.m8n8.x4.shared.b16 {%0,%1,%2,%3}, [%4];" \
        : "=r"(r0), "=r"(r1), "=r"(r2), "=r"(r3) : "r"(addr))

#define MMA16816(d, a, b0, b1) \
    asm volatile("mma.sync.aligned.m16n8k16.row.col.f32.f16.f16.f32 " \
        "{%0,%1,%2,%3}, {%4,%5,%6,%7}, {%8,%9}, {%0,%1,%2,%3};" \
        : "+f"((d)[0]), "+f"((d)[1]), "+f"((d)[2]), "+f"((d)[3]) \
        : "r"((a)[0]), "r"((a)[1]), "r"((a)[2]), "r"((a)[3]), "r"(b0), "r"(b1))

// ============================================================================
// Kernel A: rowsum -> s = rsqrt(rowsum); convert adj fp32 -> fp16.
//   (round-8 proven: 59.2us @ 76.9% DRAM) 16B-coalesced fp16 stores.
// ============================================================================
__global__ __launch_bounds__(256, 1) void gcn_rowsum_cvt_kernel(const float* __restrict__ adj) {
    int wid = threadIdx.x >> 5, lid = threadIdx.x & 31;
    int row = blockIdx.x * 8 + wid;
    const float4* r4 = (const float4*)(adj + (size_t)row * N_NODES);
    uint4* dst4 = (uint4*)(g_adj_h + (size_t)row * N_NODES);
    float s0 = 0.f, s1 = 0.f;
    #pragma unroll 4
    for (int t = lid; t < 1024; t += 64) {
        int t2 = t + 32;
        float4 a0 = r4[2 * t],  a1 = r4[2 * t + 1];
        float4 b0 = r4[2 * t2], b1 = r4[2 * t2 + 1];
        s0 += ((a0.x + a0.y) + (a0.z + a0.w)) + ((a1.x + a1.y) + (a1.z + a1.w));
        s1 += ((b0.x + b0.y) + (b0.z + b0.w)) + ((b1.x + b1.y) + (b1.z + b1.w));
        uint4 ha, hb;
        ha.x = f2h2(a0.x, a0.y); ha.y = f2h2(a0.z, a0.w);
        ha.z = f2h2(a1.x, a1.y); ha.w = f2h2(a1.z, a1.w);
        hb.x = f2h2(b0.x, b0.y); hb.y = f2h2(b0.z, b0.w);
        hb.z = f2h2(b1.x, b1.y); hb.w = f2h2(b1.z, b1.w);
        dst4[t]  = ha;
        dst4[t2] = hb;
    }
    float sum = s0 + s1;
    #pragma unroll
    for (int o = 16; o > 0; o >>= 1) sum += __shfl_xor_sync(0xFFFFFFFFu, sum, o);
    if (lid == 0) g_s[row] = (sum > 0.f) ? rsqrtf(sum) : 0.f;
}

// ============================================================================
// Kernel B: yth[d][j] = fp16( s_j * sum_k x[j,k] * W[d,k] )   (64 j-rows/block)
// ============================================================================
static constexpr int XW_SMEM = (64 * 128 + 128 * 129) * 4;  // 98816 B

__global__ __launch_bounds__(256, 1) void gcn_xw_kernel(const float* __restrict__ x,
                                                        const float* __restrict__ W) {
    extern __shared__ float sm[];
    float* xs = sm;              // [64][128]
    float* Wt = sm + 64 * 128;   // [128][129]  (k-major, padded)
    int tid = threadIdx.x;
    int j0 = blockIdx.x * 64;

    const float4* x4 = (const float4*)x + (size_t)j0 * 32;
    float4* xs4 = (float4*)xs;
    #pragma unroll
    for (int q = 0; q < 8; q++) xs4[q * 256 + tid] = x4[q * 256 + tid];

    const float4* W4 = (const float4*)W;
    #pragma unroll
    for (int q = 0; q < 16; q++) {
        int idx = q * 256 + tid;
        int d = idx >> 5, k4 = idx & 31;
        float4 w = W4[idx];
        Wt[(k4 * 4 + 0) * 129 + d] = w.x;
        Wt[(k4 * 4 + 1) * 129 + d] = w.y;
        Wt[(k4 * 4 + 2) * 129 + d] = w.z;
        Wt[(k4 * 4 + 3) * 129 + d] = w.w;
    }
    __syncthreads();

    int w = tid >> 5, l = tid & 31;
    float acc[8][4];
    #pragma unroll
    for (int a = 0; a < 8; a++)
        #pragma unroll
        for (int m = 0; m < 4; m++) acc[a][m] = 0.f;

    for (int k = 0; k < 128; k++) {
        float wv0 = Wt[k * 129 + l];
        float wv1 = Wt[k * 129 + l + 32];
        float wv2 = Wt[k * 129 + l + 64];
        float wv3 = Wt[k * 129 + l + 96];
        #pragma unroll
        for (int rr = 0; rr < 8; rr++) {
            float xv = xs[(w + rr * 8) * 128 + k];
            acc[rr][0] += xv * wv0;
            acc[rr][1] += xv * wv1;
            acc[rr][2] += xv * wv2;
            acc[rr][3] += xv * wv3;
        }
    }
    __syncthreads();

    float* yts = sm;  // reuse: [128][68]
    #pragma unroll
    for (int rr = 0; rr < 8; rr++) {
        int jj = w + rr * 8;
        float sj = g_s[j0 + jj];
        #pragma unroll
        for (int m = 0; m < 4; m++)
            yts[(l + 32 * m) * 68 + jj] = acc[rr][m] * sj;
    }
    __syncthreads();

    #pragma unroll
    for (int q = 0; q < 16; q++) {
        int idx = q * 256 + tid;      // 4096 half2 total
        int d = idx >> 5, jp = idx & 31;
        __half2 h = __floats2half2_rn(yts[d * 68 + jp * 2], yts[d * 68 + jp * 2 + 1]);
        ((__half2*)(g_yth + (size_t)d * N_NODES + j0))[jp] = h;
    }
}

// ============================================================================
// Kernel C: fp16 mma.sync GEMM, fused epilogue  out = s_i*acc + b[d]
//   CTA: M=64, N=128, BK=32, 4 stages, **128 threads, 4 warps in 2x2**
//   Warp tile 32x64: 32 MMA per 6 LDSM_X4 per chunk (ratio 0.1875),
//   A smem duplication 2x (was 4x). 80 B pitch, conflict-free LDSM.
// ============================================================================
static constexpr int GA_BYTES = 64 * 80;               // 5120  A stage
static constexpr int GB_BYTES = 128 * 80;              // 10240 B stage
static constexpr int GSTAGE   = GA_BYTES + GB_BYTES;   // 15360
static constexpr int GSTAGES  = 4;
static constexpr int GEMM_SMEM = GSTAGE * GSTAGES;     // 61440
static constexpr int NCHUNK = N_NODES / 32;            // 256

__global__ __launch_bounds__(128, 1) void gcn_gemm_kernel(const float* __restrict__ b,
                                                          float* __restrict__ out) {
    extern __shared__ char smem[];
    uint32_t sbase = smem_u32(smem);
    int tid = threadIdx.x;
    int lane = tid & 31, w = tid >> 5;
    int warp_m = w & 1, warp_n = w >> 1;          // 2x2
    int m0 = blockIdx.x * 64;

    // ---- cp.async per-thread invariants (128 threads) ----
    // A: 64 rows x 4 segs = 256 cp16 -> 2/thread (segs as, as+2)
    int ar = tid >> 1, as = tid & 1;
    const __half* Asrc = g_adj_h + (size_t)(m0 + ar) * N_NODES + as * 8;
    uint32_t a_dst = sbase + (uint32_t)(ar * 80 + as * 16);
    // B: 128 rows x 4 segs = 512 cp16 -> 4/thread (one full row)
    const __half* Bsrc = g_yth + (size_t)tid * N_NODES;
    uint32_t b_dst = sbase + GA_BYTES + (uint32_t)(tid * 80);

    // ---- ldmatrix per-lane base addresses (within stage 0) ----
    uint32_t a_lds[2], b_lds[4];
    #pragma unroll
    for (int mt = 0; mt < 2; mt++)
        a_lds[mt] = sbase + (uint32_t)((warp_m * 32 + mt * 16 + (lane & 15)) * 80
                                       + ((lane >> 4) * 16));
    #pragma unroll
    for (int np = 0; np < 4; np++)
        b_lds[np] = sbase + GA_BYTES
                  + (uint32_t)((warp_n * 64 + np * 16 + (lane & 7) + ((lane & 16) >> 1)) * 80
                               + (((lane >> 3) & 1) * 16));

    float acc[2][8][4];
    #pragma unroll
    for (int mt = 0; mt < 2; mt++)
        #pragma unroll
        for (int nt = 0; nt < 8; nt++)
            #pragma unroll
            for (int q = 0; q < 4; q++) acc[mt][nt][q] = 0.f;

    // ---- prologue: 3 stages in flight ----
    #pragma unroll
    for (int c = 0; c < GSTAGES - 1; c++) {
        uint32_t so = c * GSTAGE;
        cp_async16(a_dst + so,      Asrc + c * 32);
        cp_async16(a_dst + so + 32, Asrc + c * 32 + 16);
        #pragma unroll
        for (int q = 0; q < 4; q++)
            cp_async16(b_dst + so + q * 16, Bsrc + c * 32 + q * 8);
        cp_commit();
    }

    // ---- main loop ----
    for (int c = 0; c < NCHUNK; ++c) {
        uint32_t so = (uint32_t)(c & 3) * GSTAGE;
        asm volatile("cp.async.wait_group 2;" ::: "memory");
        __syncthreads();

        #pragma unroll
        for (int ks = 0; ks < 2; ks++) {
            uint32_t af[2][4], bf[4][4];
            LDSM_X4(af[0][0], af[0][1], af[0][2], af[0][3], a_lds[0] + so + ks * 32);
            LDSM_X4(af[1][0], af[1][1], af[1][2], af[1][3], a_lds[1] + so + ks * 32);
            #pragma unroll
            for (int np = 0; np < 4; np++)
                LDSM_X4(bf[np][0], bf[np][1], bf[np][2], bf[np][3], b_lds[np] + so + ks * 32);
            #pragma unroll
            for (int mt = 0; mt < 2; mt++)
                #pragma unroll
                for (int np = 0; np < 4; np++) {
                    MMA16816(acc[mt][2 * np + 0], af[mt], bf[np][0], bf[np][1]);
                    MMA16816(acc[mt][2 * np + 1], af[mt], bf[np][2], bf[np][3]);
                }
        }

        int cn = c + 3;
        if (cn < NCHUNK) {
            uint32_t so2 = (uint32_t)(cn & 3) * GSTAGE;
            cp_async16(a_dst + so2,      Asrc + cn * 32);
            cp_async16(a_dst + so2 + 32, Asrc + cn * 32 + 16);
            #pragma unroll
            for (int q = 0; q < 4; q++)
                cp_async16(b_dst + so2 + q * 16, Bsrc + cn * 32 + q * 8);
        }
        cp_commit();  // empty group at tail keeps wait_group bookkeeping exact
    }

    // ---- fused epilogue: out = s_i * acc + b[d] ----
    int r_base = m0 + warp_m * 32 + (lane >> 2);
    int c_base = warp_n * 64 + (lane & 3) * 2;
    #pragma unroll
    for (int mt = 0; mt < 2; mt++) {
        int r0 = r_base + mt * 16;
        float s0 = g_s[r0], s1 = g_s[r0 + 8];
        #pragma unroll
        for (int nt = 0; nt < 8; nt++) {
            int cc = c_base + nt * 8;
            float bv0 = __ldg(&b[cc]), bv1 = __ldg(&b[cc + 1]);
            float2 v0, v1;
            v0.x = s0 * acc[mt][nt][0] + bv0;
            v0.y = s0 * acc[mt][nt][1] + bv1;
            v1.x = s1 * acc[mt][nt][2] + bv0;
            v1.y = s1 * acc[mt][nt][3] + bv1;
            *(float2*)(out + (size_t)r0 * DF + cc)       = v0;
            *(float2*)(out + (size_t)(r0 + 8) * DF + cc) = v1;
        }
    }
}

// ============================================================================
extern "C" void kernel_launch(void* const* d_in, const int* in_sizes, int n_in,
                              void* d_out, int out_size) {
    const float *x = nullptr, *adj = nullptr, *W = nullptr, *b = nullptr;
    for (int i = 0; i < n_in; i++) {
        switch (in_sizes[i]) {
            case N_NODES * N_NODES: adj = (const float*)d_in[i]; break;
            case N_NODES * DF:      x   = (const float*)d_in[i]; break;
            case DF * DF:           W   = (const float*)d_in[i]; break;
            case DF:                b   = (const float*)d_in[i]; break;
        }
    }
    float* out = (float*)d_out;

    static bool attr_done = false;
    if (!attr_done) {
        cudaFuncSetAttribute(gcn_xw_kernel, cudaFuncAttributeMaxDynamicSharedMemorySize, XW_SMEM);
        cudaFuncSetAttribute(gcn_gemm_kernel, cudaFuncAttributeMaxDynamicSharedMemorySize, GEMM_SMEM);
        attr_done = true;
    }

    gcn_rowsum_cvt_kernel<<<N_NODES / 8, 256>>>(adj);
    gcn_xw_kernel<<<N_NODES / 64, 256, XW_SMEM>>>(x, W);
    gcn_gemm_kernel<<<N_NODES / 64, 128, GEMM_SMEM>>>(b, out);
}

// round 11
// speedup vs baseline: 1.2300x; 1.2300x over previous
#include <cuda_runtime.h>
#include <cuda_fp16.h>
#include <cstdint>

#define N_NODES 8192
#define DF 128

// ---------------- scratch (static __device__ globals: allocation-free) -------
__device__ float  g_s[N_NODES];                           // 32 KB : d_inv_sqrt
__device__ __half g_adj_h[(size_t)N_NODES * N_NODES];     // 128 MB: fp16 adjacency
__device__ __half g_yth[(size_t)DF * N_NODES];            // 2 MB  : (s_j*(xW^T))^T [d][j]

// ---------------- helpers ----------------------------------------------------
__device__ __forceinline__ uint32_t smem_u32(const void* p) {
    uint32_t a;
    asm("{ .reg .u64 t; cvta.to.shared.u64 t, %1; cvt.u32.u64 %0, t; }"
        : "=r"(a) : "l"(p));
    return a;
}

__device__ __forceinline__ void cp_async16(uint32_t saddr, const void* gaddr) {
    asm volatile("cp.async.cg.shared.global [%0], [%1], 16;" :: "r"(saddr), "l"(gaddr));
}
__device__ __forceinline__ void cp_commit() {
    asm volatile("cp.async.commit_group;" ::: "memory");
}

__device__ __forceinline__ uint32_t f2h2(float lo, float hi) {
    uint32_t r;
    asm("cvt.rn.f16x2.f32 %0, %1, %2;" : "=r"(r) : "f"(hi), "f"(lo));
    return r;
}

#define LDSM_X4(r0, r1, r2, r3, addr) \
    asm volatile("ldmatrix.sync.aligned.m8n8.x4.shared.b16 {%0,%1,%2,%3}, [%4];" \
        : "=r"(r0), "=r"(r1), "=r"(r2), "=r"(r3) : "r"(addr))

// fp16-accumulate MMA: D,C are 2 regs (4 halves), 2x rate vs f32-acc on legacy path
#define MMA16816H(d, a, b0, b1) \
    asm volatile("mma.sync.aligned.m16n8k16.row.col.f16.f16.f16.f16 " \
        "{%0,%1}, {%2,%3,%4,%5}, {%6,%7}, {%0,%1};" \
        : "+r"((d)[0]), "+r"((d)[1]) \
        : "r"((a)[0]), "r"((a)[1]), "r"((a)[2]), "r"((a)[3]), "r"(b0), "r"(b1))

// ============================================================================
// Kernel A: rowsum -> s = rsqrt(rowsum); convert adj fp32 -> fp16.
//   (round-10 proven: 55.8us @ 80.8% DRAM) 16B-coalesced fp16 stores.
// ============================================================================
__global__ __launch_bounds__(256, 1) void gcn_rowsum_cvt_kernel(const float* __restrict__ adj) {
    int wid = threadIdx.x >> 5, lid = threadIdx.x & 31;
    int row = blockIdx.x * 8 + wid;
    const float4* r4 = (const float4*)(adj + (size_t)row * N_NODES);
    uint4* dst4 = (uint4*)(g_adj_h + (size_t)row * N_NODES);
    float s0 = 0.f, s1 = 0.f;
    #pragma unroll 4
    for (int t = lid; t < 1024; t += 64) {
        int t2 = t + 32;
        float4 a0 = r4[2 * t],  a1 = r4[2 * t + 1];
        float4 b0 = r4[2 * t2], b1 = r4[2 * t2 + 1];
        s0 += ((a0.x + a0.y) + (a0.z + a0.w)) + ((a1.x + a1.y) + (a1.z + a1.w));
        s1 += ((b0.x + b0.y) + (b0.z + b0.w)) + ((b1.x + b1.y) + (b1.z + b1.w));
        uint4 ha, hb;
        ha.x = f2h2(a0.x, a0.y); ha.y = f2h2(a0.z, a0.w);
        ha.z = f2h2(a1.x, a1.y); ha.w = f2h2(a1.z, a1.w);
        hb.x = f2h2(b0.x, b0.y); hb.y = f2h2(b0.z, b0.w);
        hb.z = f2h2(b1.x, b1.y); hb.w = f2h2(b1.z, b1.w);
        dst4[t]  = ha;
        dst4[t2] = hb;
    }
    float sum = s0 + s1;
    #pragma unroll
    for (int o = 16; o > 0; o >>= 1) sum += __shfl_xor_sync(0xFFFFFFFFu, sum, o);
    if (lid == 0) g_s[row] = (sum > 0.f) ? rsqrtf(sum) : 0.f;
}

// ============================================================================
// Kernel B: yth[d][j] = fp16( s_j * sum_k x[j,k] * W[d,k] )   (64 j-rows/block)
// ============================================================================
static constexpr int XW_SMEM = (64 * 128 + 128 * 129) * 4;  // 98816 B

__global__ __launch_bounds__(256, 1) void gcn_xw_kernel(const float* __restrict__ x,
                                                        const float* __restrict__ W) {
    extern __shared__ float sm[];
    float* xs = sm;              // [64][128]
    float* Wt = sm + 64 * 128;   // [128][129]  (k-major, padded)
    int tid = threadIdx.x;
    int j0 = blockIdx.x * 64;

    const float4* x4 = (const float4*)x + (size_t)j0 * 32;
    float4* xs4 = (float4*)xs;
    #pragma unroll
    for (int q = 0; q < 8; q++) xs4[q * 256 + tid] = x4[q * 256 + tid];

    const float4* W4 = (const float4*)W;
    #pragma unroll
    for (int q = 0; q < 16; q++) {
        int idx = q * 256 + tid;
        int d = idx >> 5, k4 = idx & 31;
        float4 w = W4[idx];
        Wt[(k4 * 4 + 0) * 129 + d] = w.x;
        Wt[(k4 * 4 + 1) * 129 + d] = w.y;
        Wt[(k4 * 4 + 2) * 129 + d] = w.z;
        Wt[(k4 * 4 + 3) * 129 + d] = w.w;
    }
    __syncthreads();

    int w = tid >> 5, l = tid & 31;
    float acc[8][4];
    #pragma unroll
    for (int a = 0; a < 8; a++)
        #pragma unroll
        for (int m = 0; m < 4; m++) acc[a][m] = 0.f;

    for (int k = 0; k < 128; k++) {
        float wv0 = Wt[k * 129 + l];
        float wv1 = Wt[k * 129 + l + 32];
        float wv2 = Wt[k * 129 + l + 64];
        float wv3 = Wt[k * 129 + l + 96];
        #pragma unroll
        for (int rr = 0; rr < 8; rr++) {
            float xv = xs[(w + rr * 8) * 128 + k];
            acc[rr][0] += xv * wv0;
            acc[rr][1] += xv * wv1;
            acc[rr][2] += xv * wv2;
            acc[rr][3] += xv * wv3;
        }
    }
    __syncthreads();

    float* yts = sm;  // reuse: [128][68]
    #pragma unroll
    for (int rr = 0; rr < 8; rr++) {
        int jj = w + rr * 8;
        float sj = g_s[j0 + jj];
        #pragma unroll
        for (int m = 0; m < 4; m++)
            yts[(l + 32 * m) * 68 + jj] = acc[rr][m] * sj;
    }
    __syncthreads();

    #pragma unroll
    for (int q = 0; q < 16; q++) {
        int idx = q * 256 + tid;      // 4096 half2 total
        int d = idx >> 5, jp = idx & 31;
        __half2 h = __floats2half2_rn(yts[d * 68 + jp * 2], yts[d * 68 + jp * 2 + 1]);
        ((__half2*)(g_yth + (size_t)d * N_NODES + j0))[jp] = h;
    }
}

// ============================================================================
// Kernel C: fp16 mma.sync GEMM with **fp16 accumulate + windowed fp32 spill**
//   out[i,d] = s_i * sum_j adj_h[i,j]*yth[d][j] + b[d]
//   Round-3 proven structure: M=64, N=128, BK=32, 4 stages, 256 thr,
//   warps 2x4 (warp tile 32x32), 80 B pitch (conflict-free ldmatrix).
//   fp16 c-fragments accumulate 16 chunks (512 j) then spill into fp32 regs.
// ============================================================================
static constexpr int GA_BYTES = 64 * 80;      // 5120  A stage
static constexpr int GB_BYTES = 128 * 80;     // 10240 B stage
static constexpr int GSTAGE   = GA_BYTES + GB_BYTES;   // 15360
static constexpr int GSTAGES  = 4;
static constexpr int GEMM_SMEM = GSTAGE * GSTAGES;     // 61440
static constexpr int NCHUNK = N_NODES / 32;            // 256
static constexpr int WINDOW = 16;                      // chunks per fp16 window

__global__ __launch_bounds__(256, 1) void gcn_gemm_kernel(const float* __restrict__ b,
                                                          float* __restrict__ out) {
    extern __shared__ char smem[];
    uint32_t sbase = smem_u32(smem);
    int tid = threadIdx.x;
    int lane = tid & 31, w = tid >> 5;
    int warp_m = w & 1, warp_n = w >> 1;
    int m0 = blockIdx.x * 64;

    // ---- cp.async source/dest (per-thread invariants) ----
    int a_row = tid >> 2, chk = tid & 3;                 // A: 256 ops (64 rows x 4)
    const __half* Asrc  = g_adj_h + (size_t)(m0 + a_row) * N_NODES + chk * 8;
    const __half* Bsrc0 = g_yth  + (size_t)a_row * N_NODES + chk * 8;          // rows 0..63
    const __half* Bsrc1 = g_yth  + (size_t)(a_row + 64) * N_NODES + chk * 8;   // rows 64..127
    uint32_t a_dst  = sbase + a_row * 80 + chk * 16;
    uint32_t b_dst0 = sbase + GA_BYTES + a_row * 80 + chk * 16;
    uint32_t b_dst1 = b_dst0 + 64 * 80;

    // ---- ldmatrix per-lane base addresses (within stage 0) ----
    uint32_t a_lds[2], b_lds[2];
    #pragma unroll
    for (int mt = 0; mt < 2; mt++)
        a_lds[mt] = sbase + (uint32_t)((warp_m * 32 + mt * 16 + (lane & 15)) * 80
                                       + ((lane >> 4) * 16));
    #pragma unroll
    for (int np = 0; np < 2; np++)
        b_lds[np] = sbase + GA_BYTES
                  + (uint32_t)((warp_n * 32 + np * 16 + (lane & 7) + ((lane & 16) >> 1)) * 80
                               + (((lane >> 3) & 1) * 16));

    float    facc[2][4][4];   // fp32 master accumulators
    uint32_t hacc[2][4][2];   // fp16 window accumulators (4 halves per tile)
    #pragma unroll
    for (int mt = 0; mt < 2; mt++)
        #pragma unroll
        for (int nt = 0; nt < 4; nt++) {
            #pragma unroll
            for (int q = 0; q < 4; q++) facc[mt][nt][q] = 0.f;
            hacc[mt][nt][0] = 0u; hacc[mt][nt][1] = 0u;
        }

    // ---- prologue: 3 stages in flight ----
    #pragma unroll
    for (int c = 0; c < GSTAGES - 1; c++) {
        uint32_t so = c * GSTAGE;
        cp_async16(a_dst  + so, Asrc  + c * 32);
        cp_async16(b_dst0 + so, Bsrc0 + c * 32);
        cp_async16(b_dst1 + so, Bsrc1 + c * 32);
        cp_commit();
    }

    // ---- main loop ----
    for (int c = 0; c < NCHUNK; ++c) {
        uint32_t so = (uint32_t)(c & 3) * GSTAGE;
        asm volatile("cp.async.wait_group 2;" ::: "memory");
        __syncthreads();

        #pragma unroll
        for (int ks = 0; ks < 2; ks++) {
            uint32_t af[2][4], bf[2][4];
            LDSM_X4(af[0][0], af[0][1], af[0][2], af[0][3], a_lds[0] + so + ks * 32);
            LDSM_X4(af[1][0], af[1][1], af[1][2], af[1][3], a_lds[1] + so + ks * 32);
            LDSM_X4(bf[0][0], bf[0][1], bf[0][2], bf[0][3], b_lds[0] + so + ks * 32);
            LDSM_X4(bf[1][0], bf[1][1], bf[1][2], bf[1][3], b_lds[1] + so + ks * 32);
            #pragma unroll
            for (int mt = 0; mt < 2; mt++) {
                MMA16816H(hacc[mt][0], af[mt], bf[0][0], bf[0][1]);
                MMA16816H(hacc[mt][1], af[mt], bf[0][2], bf[0][3]);
                MMA16816H(hacc[mt][2], af[mt], bf[1][0], bf[1][1]);
                MMA16816H(hacc[mt][3], af[mt], bf[1][2], bf[1][3]);
            }
        }

        // ---- window spill: fp16 -> fp32 every WINDOW chunks ----
        if ((c & (WINDOW - 1)) == (WINDOW - 1)) {
            #pragma unroll
            for (int mt = 0; mt < 2; mt++)
                #pragma unroll
                for (int nt = 0; nt < 4; nt++) {
                    float2 lo = __half22float2(*(__half2*)&hacc[mt][nt][0]);
                    float2 hi = __half22float2(*(__half2*)&hacc[mt][nt][1]);
                    facc[mt][nt][0] += lo.x;
                    facc[mt][nt][1] += lo.y;
                    facc[mt][nt][2] += hi.x;
                    facc[mt][nt][3] += hi.y;
                    hacc[mt][nt][0] = 0u; hacc[mt][nt][1] = 0u;
                }
        }

        int cn = c + 3;
        if (cn < NCHUNK) {
            uint32_t so2 = (uint32_t)(cn & 3) * GSTAGE;
            cp_async16(a_dst  + so2, Asrc  + cn * 32);
            cp_async16(b_dst0 + so2, Bsrc0 + cn * 32);
            cp_async16(b_dst1 + so2, Bsrc1 + cn * 32);
        }
        cp_commit();  // empty group at tail keeps wait_group bookkeeping exact
    }

    // ---- fused epilogue: out = s_i * facc + b[d] ----
    int r_base = m0 + warp_m * 32 + (lane >> 2);
    int c_base = warp_n * 32 + (lane & 3) * 2;
    #pragma unroll
    for (int mt = 0; mt < 2; mt++) {
        int r0 = r_base + mt * 16;
        float s0 = g_s[r0], s1 = g_s[r0 + 8];
        #pragma unroll
        for (int nt = 0; nt < 4; nt++) {
            int cc = c_base + nt * 8;
            float bv0 = __ldg(&b[cc]), bv1 = __ldg(&b[cc + 1]);
            float2 v0, v1;
            v0.x = s0 * facc[mt][nt][0] + bv0;
            v0.y = s0 * facc[mt][nt][1] + bv1;
            v1.x = s1 * facc[mt][nt][2] + bv0;
            v1.y = s1 * facc[mt][nt][3] + bv1;
            *(float2*)(out + (size_t)r0 * DF + cc)       = v0;
            *(float2*)(out + (size_t)(r0 + 8) * DF + cc) = v1;
        }
    }
}

// ============================================================================
extern "C" void kernel_launch(void* const* d_in, const int* in_sizes, int n_in,
                              void* d_out, int out_size) {
    const float *x = nullptr, *adj = nullptr, *W = nullptr, *b = nullptr;
    for (int i = 0; i < n_in; i++) {
        switch (in_sizes[i]) {
            case N_NODES * N_NODES: adj = (const float*)d_in[i]; break;
            case N_NODES * DF:      x   = (const float*)d_in[i]; break;
            case DF * DF:           W   = (const float*)d_in[i]; break;
            case DF:                b   = (const float*)d_in[i]; break;
        }
    }
    float* out = (float*)d_out;

    static bool attr_done = false;
    if (!attr_done) {
        cudaFuncSetAttribute(gcn_xw_kernel, cudaFuncAttributeMaxDynamicSharedMemorySize, XW_SMEM);
        cudaFuncSetAttribute(gcn_gemm_kernel, cudaFuncAttributeMaxDynamicSharedMemorySize, GEMM_SMEM);
        attr_done = true;
    }

    gcn_rowsum_cvt_kernel<<<N_NODES / 8, 256>>>(adj);
    gcn_xw_kernel<<<N_NODES / 64, 256, XW_SMEM>>>(x, W);
    gcn_gemm_kernel<<<N_NODES / 64, 256, GEMM_SMEM>>>(b, out);
}